// round 16
// baseline (speedup 1.0000x reference)
#include <cuda_runtime.h>
#include <cuda_bf16.h>
#include <cstdint>

// ---------------------------------------------------------------------------
// DeltaOnlyModel: B=256, L=2048, H=V=64.
// Gram-basis state: M = sum_c U[c] k_c^T. ONE WARP PER BATCH, two batches per
// 64-thread block (warp w -> batch 2*blockIdx+w). Thread `lane` owns hidden
// rows lane and lane+32 of U in thread-private smem. The 10 quad S-sums are a
// pure intra-warp butterfly: NO smem exchange, NO __syncthreads in the loop.
// Quad chunking + exact in-quad gate algebra (validated R3/R11/R15).
// ---------------------------------------------------------------------------

#define H 64
#define V 64
#define L 2048
#define B 256
#define TSTR 132              // per-thread U stride (floats): 132 = 4 mod 32
#define UWRP (32 * TSTR)      // per-warp U region (floats)

// dynamic smem layout (float offsets)
#define OFF_G    0
#define OFF_V    (V * V)
#define OFF_U    (OFF_V + V * H)
#define OFF_X    (OFF_U + 2 * UWRP)          // ints (2 batches x L)
#define OFF_THR  (OFF_X + 2 * L)
#define OFF_FIN  (OFF_THR + V)
#define SMEM_FLOATS (OFF_FIN + 2 * H)
#define SMEM_BYTES  (SMEM_FLOATS * 4)

__device__ float g_ktab[V * H];
__device__ float g_vtab[V * H];
__device__ float g_qtab[V * H];
__device__ float g_gram[V * V];     // G[a][b]  = k_a . k_b (symmetric)
__device__ float g_gramqT[V * V];   // GqT[b][a] = k_a . q_b
__device__ float g_thr2[V];

typedef unsigned long long ull;

__device__ __forceinline__ ull ffma2(ull a, ull b, ull c) {
    ull d;
    asm("fma.rn.f32x2 %0, %1, %2, %3;" : "=l"(d) : "l"(a), "l"(b), "l"(c));
    return d;
}
__device__ __forceinline__ ull fadd2(ull a, ull b) {
    ull d;
    asm("add.rn.f32x2 %0, %1, %2;" : "=l"(d) : "l"(a), "l"(b));
    return d;
}
__device__ __forceinline__ ull pack2(float lo, float hi) {
    ull d;
    asm("mov.b64 %0, {%1, %2};" : "=l"(d) : "f"(lo), "f"(hi));
    return d;
}
__device__ __forceinline__ void unpack2(ull a, float& lo, float& hi) {
    asm("mov.b64 {%0, %1}, %2;" : "=f"(lo), "=f"(hi) : "l"(a));
}
__device__ __forceinline__ float hsum2p(ull a, ull b) {
    float lo, hi;
    unpack2(fadd2(a, b), lo, hi);
    return lo + hi;
}

// ---------------------------------------------------------------------------
// Table builder: one block per vocab entry, 64 threads.
// ---------------------------------------------------------------------------
__global__ void build_tables(const float* __restrict__ embed,
                             const float* __restrict__ w1,
                             const float* __restrict__ b1,
                             const float* __restrict__ w2,
                             const float* __restrict__ b2,
                             const float* __restrict__ ln_g,
                             const float* __restrict__ ln_b,
                             const float* __restrict__ wk,
                             const float* __restrict__ wv,
                             const float* __restrict__ wq) {
    __shared__ float se[H];
    __shared__ float su[2 * H];
    __shared__ float sh[H];
    __shared__ float sred[H];

    const int c = blockIdx.x;
    const int j = threadIdx.x;

    se[j] = embed[c * H + j];
    __syncthreads();

    #pragma unroll
    for (int rep = 0; rep < 2; rep++) {
        const int m = j + rep * H;
        float a = b1[m];
        #pragma unroll 8
        for (int i = 0; i < H; i++) a = fmaf(se[i], w1[i * (2 * H) + m], a);
        su[m] = fmaxf(a, 0.0f);
    }
    __syncthreads();

    float f = b2[j];
    #pragma unroll 8
    for (int m = 0; m < 2 * H; m++) f = fmaf(su[m], w2[m * H + j], f);

    const float s = se[j] + f;
    sh[j] = s;
    __syncthreads();

    float mu = 0.0f;
    #pragma unroll 8
    for (int i = 0; i < H; i++) mu += sh[i];
    mu *= (1.0f / H);
    float var = 0.0f;
    #pragma unroll 8
    for (int i = 0; i < H; i++) { float d = sh[i] - mu; var = fmaf(d, d, var); }
    var *= (1.0f / H);
    const float hn = (s - mu) * rsqrtf(var + 1e-5f) * ln_g[j] + ln_b[j];
    __syncthreads();
    sh[j] = hn;
    __syncthreads();

    float kr = 0.0f;
    #pragma unroll 8
    for (int i = 0; i < H; i++) kr = fmaf(sh[i], wk[i * H + j], kr);
    sred[j] = kr * kr;
    __syncthreads();
    float nk = 0.0f;
    #pragma unroll 8
    for (int i = 0; i < H; i++) nk += sred[i];
    nk = fmaxf(sqrtf(nk), 1e-12f);
    g_ktab[c * H + j] = kr / nk;
    __syncthreads();

    float vr = 0.0f;
    #pragma unroll 8
    for (int i = 0; i < H; i++) vr = fmaf(sh[i], wv[i * H + j], vr);
    g_vtab[c * H + j] = vr;
    sred[j] = vr * vr;
    __syncthreads();
    float nv = 0.0f;
    #pragma unroll 8
    for (int i = 0; i < H; i++) nv += sred[i];
    if (j == 0) g_thr2[c] = 0.16f * nv;

    float qr = 0.0f;
    #pragma unroll 8
    for (int i = 0; i < H; i++) qr = fmaf(sh[i], wq[i * H + j], qr);
    g_qtab[c * H + j] = qr;
}

// Gram matrices: G[a][b] = k_a.k_b ; GqT[b][a] = k_a.q_b
__global__ void gram_kernel() {
    __shared__ float ka[H];
    const int a = blockIdx.x;
    const int j = threadIdx.x;
    ka[j] = g_ktab[a * H + j];
    __syncthreads();
    float s = 0.0f, sq = 0.0f;
    #pragma unroll 8
    for (int i = 0; i < H; i++) {
        s  = fmaf(ka[i], g_ktab[j * H + i], s);
        sq = fmaf(ka[i], g_qtab[j * H + i], sq);
    }
    g_gram[a * H + j]   = s;
    g_gramqT[j * H + a] = sq;
}

// ---------------------------------------------------------------------------
// Scan kernel: one warp per batch, exchange-free quad reduction.
// ---------------------------------------------------------------------------
__global__ __launch_bounds__(64) void scan_kernel(const int* __restrict__ x,
                                                  const float* __restrict__ wo,
                                                  const float* __restrict__ bo,
                                                  float* __restrict__ out) {
    extern __shared__ __align__(16) float smem[];
    float* sG   = smem + OFF_G;
    float* sv   = smem + OFF_V;
    float* sU   = smem + OFF_U;
    int*   sx   = reinterpret_cast<int*>(smem + OFF_X);
    float* sthr = smem + OFF_THR;
    float* sfin = smem + OFF_FIN;

    const int tid  = threadIdx.x;
    const int lane = tid & 31;
    const int w    = tid >> 5;
    const int batch = (blockIdx.x << 1) + w;

    // cooperative table loads (block-wide, once)
    for (int i = tid; i < V * V; i += 64) sG[i] = g_gram[i];
    for (int i = tid; i < V * H; i += 64) sv[i] = g_vtab[i];
    if (tid < V) sthr[tid] = g_thr2[tid];
    {
        const int base = (blockIdx.x << 1) * L;
        for (int i = tid; i < 2 * L; i += 64) sx[i] = x[base + i];
    }
    // zero this thread's U rows (rowA = [0,64), rowB = [64,128) of its slab)
    float* Urow = sU + w * UWRP + lane * TSTR;
    {
        const float4 z = make_float4(0.f, 0.f, 0.f, 0.f);
        #pragma unroll
        for (int j = 0; j < 32; j++) reinterpret_cast<float4*>(Urow)[j] = z;
    }
    __syncthreads();   // the only block sync before readout

    const int* sxw = sx + w * L;
    const ulonglong2* UpA = reinterpret_cast<const ulonglong2*>(Urow);
    const ulonglong2* UpB = reinterpret_cast<const ulonglong2*>(Urow + 64);

    int tk0 = sxw[0], tk1 = sxw[1], tk2 = sxw[2], tk3 = sxw[3];
    float vA0 = sv[(tk0 << 6) + lane],      vB0 = sv[(tk0 << 6) + lane + 32];
    float vA1 = sv[(tk1 << 6) + lane],      vB1 = sv[(tk1 << 6) + lane + 32];
    float vA2 = sv[(tk2 << 6) + lane],      vB2 = sv[(tk2 << 6) + lane + 32];
    float vA3 = sv[(tk3 << 6) + lane],      vB3 = sv[(tk3 << 6) + lane + 32];

    for (int t = 0; t < L; t += 4) {
        // prefetch next quad
        const int nt = (t + 4) & (L - 1);
        const int nk0 = sxw[nt], nk1 = sxw[nt + 1], nk2 = sxw[nt + 2], nk3 = sxw[nt + 3];
        const float nA0 = sv[(nk0 << 6) + lane], nB0 = sv[(nk0 << 6) + lane + 32];
        const float nA1 = sv[(nk1 << 6) + lane], nB1 = sv[(nk1 << 6) + lane + 32];
        const float nA2 = sv[(nk2 << 6) + lane], nB2 = sv[(nk2 << 6) + lane + 32];
        const float nA3 = sv[(nk3 << 6) + lane], nB3 = sv[(nk3 << 6) + lane + 32];

        // gate scalars (broadcast)
        const float thr0 = sthr[tk0], thr1 = sthr[tk1];
        const float thr2 = sthr[tk2], thr3 = sthr[tk3];
        const float G01 = sG[(tk0 << 6) + tk1];
        const float G02 = sG[(tk0 << 6) + tk2];
        const float G03 = sG[(tk0 << 6) + tk3];
        const float G12 = sG[(tk1 << 6) + tk2];
        const float G13 = sG[(tk1 << 6) + tk3];
        const float G23 = sG[(tk2 << 6) + tk3];

        // preds for 4 tokens x 2 rows: P = sum_c U[c][i] * G[tok][c]
        const ulonglong2* g0p = reinterpret_cast<const ulonglong2*>(sG + (tk0 << 6));
        const ulonglong2* g1p = reinterpret_cast<const ulonglong2*>(sG + (tk1 << 6));
        const ulonglong2* g2p = reinterpret_cast<const ulonglong2*>(sG + (tk2 << 6));
        const ulonglong2* g3p = reinterpret_cast<const ulonglong2*>(sG + (tk3 << 6));
        ull aA0 = 0, aA1 = 0, bA0 = 0, bA1 = 0, cA0 = 0, cA1 = 0, dA0 = 0, dA1 = 0;
        ull aB0 = 0, aB1 = 0, bB0 = 0, bB1 = 0, cB0 = 0, cB1 = 0, dB0 = 0, dB1 = 0;
        #pragma unroll
        for (int j = 0; j < 16; j++) {
            const ulonglong2 uA = UpA[j];
            const ulonglong2 uB = UpB[j];
            const ulonglong2 G0 = g0p[j];
            const ulonglong2 G1 = g1p[j];
            const ulonglong2 G2 = g2p[j];
            const ulonglong2 G3 = g3p[j];
            aA0 = ffma2(uA.x, G0.x, aA0); aA1 = ffma2(uA.y, G0.y, aA1);
            bA0 = ffma2(uA.x, G1.x, bA0); bA1 = ffma2(uA.y, G1.y, bA1);
            cA0 = ffma2(uA.x, G2.x, cA0); cA1 = ffma2(uA.y, G2.y, cA1);
            dA0 = ffma2(uA.x, G3.x, dA0); dA1 = ffma2(uA.y, G3.y, dA1);
            aB0 = ffma2(uB.x, G0.x, aB0); aB1 = ffma2(uB.y, G0.y, aB1);
            bB0 = ffma2(uB.x, G1.x, bB0); bB1 = ffma2(uB.y, G1.y, bB1);
            cB0 = ffma2(uB.x, G2.x, cB0); cB1 = ffma2(uB.y, G2.y, cB1);
            dB0 = ffma2(uB.x, G3.x, dB0); dB1 = ffma2(uB.y, G3.y, dB1);
        }
        const float rA0 = vA0 - hsum2p(aA0, aA1);
        const float rA1 = vA1 - hsum2p(bA0, bA1);
        const float rA2 = vA2 - hsum2p(cA0, cA1);
        const float rA3 = vA3 - hsum2p(dA0, dA1);
        const float rB0 = vB0 - hsum2p(aB0, aB1);
        const float rB1 = vB1 - hsum2p(bB0, bB1);
        const float rB2 = vB2 - hsum2p(cB0, cB1);
        const float rB3 = vB3 - hsum2p(dB0, dB1);

        // 10 S-sums packed as 5 f32x2; pure intra-warp butterfly
        ull u0 = pack2(fmaf(rA0, rA0, rB0 * rB0), fmaf(rA0, rA1, rB0 * rB1));
        ull u1 = pack2(fmaf(rA0, rA2, rB0 * rB2), fmaf(rA0, rA3, rB0 * rB3));
        ull u2 = pack2(fmaf(rA1, rA1, rB1 * rB1), fmaf(rA1, rA2, rB1 * rB2));
        ull u3 = pack2(fmaf(rA1, rA3, rB1 * rB3), fmaf(rA2, rA2, rB2 * rB2));
        ull u4 = pack2(fmaf(rA2, rA3, rB2 * rB3), fmaf(rA3, rA3, rB3 * rB3));
        #pragma unroll
        for (int o = 16; o > 0; o >>= 1) {
            u0 = fadd2(u0, __shfl_xor_sync(0xffffffffu, u0, o));
            u1 = fadd2(u1, __shfl_xor_sync(0xffffffffu, u1, o));
            u2 = fadd2(u2, __shfl_xor_sync(0xffffffffu, u2, o));
            u3 = fadd2(u3, __shfl_xor_sync(0xffffffffu, u3, o));
            u4 = fadd2(u4, __shfl_xor_sync(0xffffffffu, u4, o));
        }
        float S00, S01, S02, S03, S11, S12, S13, S22, S23, S33;
        unpack2(u0, S00, S01);
        unpack2(u1, S02, S03);
        unpack2(u2, S11, S12);
        unpack2(u3, S13, S22);
        unpack2(u4, S23, S33);

        // exact in-quad gate algebra (validated R3/R11/R15)
        const bool g0b = S00 > thr0;
        const float w10 = g0b ? -G01 : 0.0f;
        const float n1s = S11 + w10 * (2.0f * S01 + w10 * S00);
        const bool g1b = n1s > thr1;
        const float w21 = g1b ? -G12 : 0.0f;
        const float w20 = (g0b ? -G02 : 0.0f) + w21 * w10;
        const float n2s = S22 + w20 * (w20 * S00 + 2.0f * S02)
                              + w21 * (w21 * S11 + 2.0f * S12)
                              + 2.0f * w20 * w21 * S01;
        const bool g2b = n2s > thr2;
        const float w32 = g2b ? -G23 : 0.0f;
        const float t13 = g1b ? -G13 : 0.0f;
        const float w31 = t13 + w32 * w21;
        const float w30 = (g0b ? -G03 : 0.0f) + t13 * w10 + w32 * w20;
        const float n3s = S33 + w30 * (w30 * S00 + 2.0f * S03)
                              + w31 * (w31 * S11 + 2.0f * S13)
                              + w32 * (w32 * S22 + 2.0f * S23)
                              + 2.0f * (w30 * w31 * S01 + w30 * w32 * S02 + w31 * w32 * S12);
        const bool g3b = n3s > thr3;

        // state update: scalar RMWs on thread-private rows (warp-uniform branch)
        if (g0b | g1b | g2b | g3b) {
            if (g0b) { Urow[tk0] += rA0;                         Urow[64 + tk0] += rB0; }
            if (g1b) { Urow[tk1] += fmaf(w10, rA0, rA1);         Urow[64 + tk1] += fmaf(w10, rB0, rB1); }
            if (g2b) { Urow[tk2] += rA2 + w20 * rA0 + w21 * rA1; Urow[64 + tk2] += rB2 + w20 * rB0 + w21 * rB1; }
            if (g3b) { Urow[tk3] += rA3 + w30 * rA0 + w31 * rA1 + w32 * rA2;
                       Urow[64 + tk3] += rB3 + w30 * rB0 + w31 * rB1 + w32 * rB2; }
        }

        tk0 = nk0; tk1 = nk1; tk2 = nk2; tk3 = nk3;
        vA0 = nA0; vA1 = nA1; vA2 = nA2; vA3 = nA3;
        vB0 = nB0; vB1 = nB1; vB2 = nB2; vB3 = nB3;
    }

    // Readout: read_i = relu( sum_c U[c][i] * (k_c . q_tokL) )
    const int tokL = sxw[L - 1];
    const ulonglong2* gq = reinterpret_cast<const ulonglong2*>(g_gramqT + (tokL << 6));
    ull s0 = 0, s1 = 0, s2 = 0, s3 = 0;
    #pragma unroll
    for (int j = 0; j < 16; j++) {
        const ulonglong2 qq = gq[j];
        const ulonglong2 uA = UpA[j];
        const ulonglong2 uB = UpB[j];
        s0 = ffma2(uA.x, qq.x, s0); s1 = ffma2(uA.y, qq.y, s1);
        s2 = ffma2(uB.x, qq.x, s2); s3 = ffma2(uB.y, qq.y, s3);
    }
    float* sfinw = sfin + w * H;
    sfinw[lane]      = fmaxf(hsum2p(s0, s1), 0.0f);
    sfinw[lane + 32] = fmaxf(hsum2p(s2, s3), 0.0f);
    __syncwarp();

    #pragma unroll
    for (int rep = 0; rep < 2; rep++) {
        const int col = lane + rep * 32;
        float oacc = bo[col];
        #pragma unroll 8
        for (int i = 0; i < H; i++) oacc = fmaf(sfinw[i], wo[(i << 6) + col], oacc);
        out[(batch << 6) + col] = oacc;
    }
}

// ---------------------------------------------------------------------------
// Inputs: x, embed, w1, b1, w2, b2, ln_g, ln_b, wk, wv, wq, wo, bo
// ---------------------------------------------------------------------------
extern "C" void kernel_launch(void* const* d_in, const int* in_sizes, int n_in,
                              void* d_out, int out_size) {
    const int*   x     = (const int*)d_in[0];
    const float* embed = (const float*)d_in[1];
    const float* w1    = (const float*)d_in[2];
    const float* b1    = (const float*)d_in[3];
    const float* w2    = (const float*)d_in[4];
    const float* b2    = (const float*)d_in[5];
    const float* ln_g  = (const float*)d_in[6];
    const float* ln_b  = (const float*)d_in[7];
    const float* wk    = (const float*)d_in[8];
    const float* wv    = (const float*)d_in[9];
    const float* wq    = (const float*)d_in[10];
    const float* wo    = (const float*)d_in[11];
    const float* bo    = (const float*)d_in[12];
    float*       out   = (float*)d_out;

    static bool attr_set = false;
    if (!attr_set) {
        cudaFuncSetAttribute(scan_kernel,
                             cudaFuncAttributeMaxDynamicSharedMemorySize,
                             SMEM_BYTES);
        attr_set = true;
    }

    build_tables<<<V, H>>>(embed, w1, b1, w2, b2, ln_g, ln_b, wk, wv, wq);
    gram_kernel<<<V, H>>>();
    scan_kernel<<<B / 2, 64, SMEM_BYTES>>>(x, wo, bo, out);
}